// round 6
// baseline (speedup 1.0000x reference)
#include <cuda_runtime.h>
#include <cuda_bf16.h>
#include <stdint.h>

#define BATCH   2048
#define N0      49
#define CH      768
#define HC      384          /* channels per CTA (half) */
#define MID     48
#define K1      36
#define K2      24
#define THREADS 512
#define WARPS   16

// Preprocessed weights (device globals).
//   g_w1t[r][j*CH + c] = bf16( se{r}_w1[c, j] )  transposed -> coalesced GEMV
//   g_w2 [r][j*CH + c] = bf16( se{r}_w2[j, c] )
//   g_clswt[o*CH + c]  = cls_w[c, o]             transposed, fp32
__device__ __nv_bfloat16 g_w1t[2][MID * CH];
__device__ __nv_bfloat16 g_w2 [2][MID * CH];
__device__ float         g_clswt[5 * CH];

__global__ void convert_weights_kernel(const float* __restrict__ w1a,
                                       const float* __restrict__ w2a,
                                       const float* __restrict__ w1b,
                                       const float* __restrict__ w2b,
                                       const float* __restrict__ clsw) {
    int i = blockIdx.x * blockDim.x + threadIdx.x;
    if (i < MID * CH) {
        int j = i / CH;
        int c = i - j * CH;
        g_w1t[0][i] = __float2bfloat16(w1a[c * MID + j]);
        g_w1t[1][i] = __float2bfloat16(w1b[c * MID + j]);
        g_w2 [0][i] = __float2bfloat16(w2a[i]);
        g_w2 [1][i] = __float2bfloat16(w2b[i]);
    }
    if (i < 5 * CH) {
        int o = i / CH;
        int c = i - o * CH;
        g_clswt[i] = clsw[c * 5 + o];
    }
}

// ---------------- cluster / DSMEM helpers ----------------
__device__ __forceinline__ uint32_t smem_u32(const void* p) {
    uint32_t a;
    asm("{ .reg .u64 t; cvta.to.shared.u64 t, %1; cvt.u32.u64 %0, t; }"
        : "=r"(a) : "l"(p));
    return a;
}
__device__ __forceinline__ uint32_t my_ctarank() {
    uint32_t r;
    asm("mov.u32 %0, %%cluster_ctarank;" : "=r"(r));
    return r;
}
__device__ __forceinline__ float peer_ldf(uint32_t local_addr, uint32_t peer) {
    uint32_t ra; float v;
    asm("mapa.shared::cluster.u32 %0, %1, %2;" : "=r"(ra) : "r"(local_addr), "r"(peer));
    asm volatile("ld.shared::cluster.f32 %0, [%1];" : "=f"(v) : "r"(ra));
    return v;
}
__device__ __forceinline__ void cluster_sync() {
    asm volatile("barrier.cluster.arrive.aligned;" ::: "memory");
    asm volatile("barrier.cluster.wait.aligned;" ::: "memory");
}

// Shared memory layout (per CTA):
//   tile  [N0*HC] f32 = 75264 B     (all 49 rows, own channel half)
//   sbuf  [HC], gat [HC], hbuf [MID]
//   ts[64], list[64] int, nlist[64] int, red[32]
//   exchange slots: xh1[48], xts1[64], xh2[48], xts2[64], xln[8], xcls[8]
#define SM_BYTES ((N0*HC + HC + HC + MID + 64 + 64 + 64 + 32 + 48 + 64 + 48 + 64 + 8 + 8) * 4)

__global__ __launch_bounds__(THREADS, 2) __cluster_dims__(2, 1, 1)
void coatgft_kernel(const float* __restrict__ x,
                    const float* __restrict__ b1a, const float* __restrict__ b2a,
                    const float* __restrict__ b1b, const float* __restrict__ b2b,
                    const float* __restrict__ ln_g, const float* __restrict__ ln_b,
                    const float* __restrict__ cls_b,
                    float* __restrict__ out) {
    extern __shared__ float sm[];
    float* tile  = sm;                    // [N0*HC]
    float* sbuf  = tile + N0 * HC;        // [HC]
    float* gat   = sbuf + HC;             // [HC]
    float* hbuf  = gat + HC;              // [MID]
    float* ts    = hbuf + MID;            // [64]
    int*   list  = (int*)(ts + 64);       // [64]
    int*   nlist = list + 64;             // [64]
    float* red   = (float*)(nlist + 64);  // [32]
    float* xh1   = red + 32;              // [48]
    float* xts1  = xh1 + 48;              // [64]
    float* xh2   = xts1 + 64;             // [48]
    float* xts2  = xh2 + 48;              // [64]
    float* xln   = xts2 + 64;             // [8]
    float* xcls  = xln + 8;               // [8]

    const int tid  = threadIdx.x;
    const int lane = tid & 31;
    const int warp = tid >> 5;
    const uint32_t rank = my_ctarank();
    const uint32_t peer = rank ^ 1u;
    const int b    = blockIdx.x >> 1;
    const int hb   = (int)rank * HC;      // channel base

    // ---------------- load own channel half: 49 rows x 384 ch (fp32) --------
    {
        const float* xb = x + (size_t)b * N0 * CH + hb;
        #pragma unroll
        for (int k = 0; k < 10; k++) {
            int i = tid + k * THREADS;          // f4 index, row = i/96, col = i%96
            if (i < N0 * HC / 4) {
                int r  = i / (HC / 4);
                int c4 = i - r * (HC / 4);
                float4 v = *(const float4*)(xb + r * CH + 4 * c4);
                *(float4*)(tile + r * HC + 4 * c4) = v;
            }
        }
    }
    __syncthreads();

    // ---------------- colmean over 49 rows (local, own channels) ------------
    if (tid < HC) {
        float acc = 0.f;
        #pragma unroll
        for (int r = 0; r < N0; r++) acc += tile[r * HC + tid];
        sbuf[tid] = acc * (1.0f / (float)N0);
    }
    __syncthreads();

    // ================= ROUND 1 =================
    // h partials over own channels: 3 outputs per warp
    {
        const __nv_bfloat162* W1t = (const __nv_bfloat162*)g_w1t[0];
        #pragma unroll
        for (int jj = 0; jj < 3; jj++) {
            int j = warp + jj * WARPS;
            const __nv_bfloat162* wr = W1t + (j * CH + hb) / 2;
            float acc = 0.f;
            #pragma unroll
            for (int k = 0; k < HC / 64; k++) {      // 6 iters of bf162 pairs
                int p = lane + 32 * k;
                __nv_bfloat162 w = wr[p];
                acc += sbuf[2 * p] * __low2float(w) + sbuf[2 * p + 1] * __high2float(w);
            }
            #pragma unroll
            for (int o = 16; o; o >>= 1) acc += __shfl_xor_sync(0xffffffffu, acc, o);
            if (lane == 0) xh1[j] = acc;
        }
    }
    cluster_sync();                                   // #1
    if (tid < MID) {
        float hf = xh1[tid] + peer_ldf(smem_u32(&xh1[tid]), peer);
        float z = hf + b1a[tid];
        hbuf[tid] = 0.5f * z * (1.0f + erff(z * 0.70710678118654752f));
    }
    __syncthreads();

    // gates1 (own channels)
    if (tid < HC) {
        const __nv_bfloat16* W2 = g_w2[0] + hb;
        float acc = b2a[hb + tid];
        #pragma unroll
        for (int j = 0; j < MID; j++)
            acc += hbuf[j] * __bfloat162float(W2[j * CH + tid]);
        gat[tid] = 1.0f / (1.0f + expf(-acc));
    }
    __syncthreads();

    // ts partials (fp32 exact): rows across 16 warps
    #pragma unroll
    for (int ii = 0; ii < 4; ii++) {
        int r = warp + ii * WARPS;
        if (r < N0) {
            const float* row = tile + r * HC;
            float acc = 0.f;
            #pragma unroll
            for (int k = 0; k < HC / 32; k++) {
                float v = row[lane + 32 * k] * gat[lane + 32 * k];
                acc += v * v;
            }
            #pragma unroll
            for (int o = 16; o; o >>= 1) acc += __shfl_xor_sync(0xffffffffu, acc, o);
            if (lane == 0) xts1[r] = acc;
        }
    }
    cluster_sync();                                   // #2
    if (tid < N0)
        ts[tid] = xts1[tid] + peer_ldf(smem_u32(&xts1[tid]), peer);
    __syncthreads();

    // rank-select top-36 (identical in both CTAs; rank order == jax top_k)
    if (tid < N0) {
        float mine = ts[tid];
        int r = 0;
        #pragma unroll
        for (int j = 0; j < N0; j++) {
            float tj = ts[j];
            r += (tj > mine) || (tj == mine && j < tid);
        }
        if (r < K1) nlist[r] = tid;
    }
    __syncthreads();
    if (tid < K1) list[tid] = nlist[tid];
    __syncthreads();

    // ================= ROUND 2 =================
    // s2 = gate * colsum(selected 36)/36  (local)
    if (tid < HC) {
        float acc = 0.f;
        #pragma unroll
        for (int i = 0; i < K1; i++) acc += tile[list[i] * HC + tid];
        sbuf[tid] = acc * gat[tid] * (1.0f / (float)K1);
    }
    __syncthreads();

    {
        const __nv_bfloat162* W1t = (const __nv_bfloat162*)g_w1t[1];
        #pragma unroll
        for (int jj = 0; jj < 3; jj++) {
            int j = warp + jj * WARPS;
            const __nv_bfloat162* wr = W1t + (j * CH + hb) / 2;
            float acc = 0.f;
            #pragma unroll
            for (int k = 0; k < HC / 64; k++) {
                int p = lane + 32 * k;
                __nv_bfloat162 w = wr[p];
                acc += sbuf[2 * p] * __low2float(w) + sbuf[2 * p + 1] * __high2float(w);
            }
            #pragma unroll
            for (int o = 16; o; o >>= 1) acc += __shfl_xor_sync(0xffffffffu, acc, o);
            if (lane == 0) xh2[j] = acc;
        }
    }
    cluster_sync();                                   // #3
    if (tid < MID) {
        float hf = xh2[tid] + peer_ldf(smem_u32(&xh2[tid]), peer);
        float z = hf + b1b[tid];
        hbuf[tid] = 0.5f * z * (1.0f + erff(z * 0.70710678118654752f));
    }
    __syncthreads();

    if (tid < HC) {
        const __nv_bfloat16* W2 = g_w2[1] + hb;
        float acc = b2b[hb + tid];
        #pragma unroll
        for (int j = 0; j < MID; j++)
            acc += hbuf[j] * __bfloat162float(W2[j * CH + tid]);
        gat[tid] *= 1.0f / (1.0f + expf(-acc));
    }
    __syncthreads();

    #pragma unroll
    for (int ii = 0; ii < 3; ii++) {
        int i = warp + ii * WARPS;
        if (i < K1) {
            const float* row = tile + list[i] * HC;
            float acc = 0.f;
            #pragma unroll
            for (int k = 0; k < HC / 32; k++) {
                float v = row[lane + 32 * k] * gat[lane + 32 * k];
                acc += v * v;
            }
            #pragma unroll
            for (int o = 16; o; o >>= 1) acc += __shfl_xor_sync(0xffffffffu, acc, o);
            if (lane == 0) xts2[i] = acc;
        }
    }
    cluster_sync();                                   // #4
    if (tid < K1)
        ts[tid] = xts2[tid] + peer_ldf(smem_u32(&xts2[tid]), peer);
    __syncthreads();

    if (tid < K1) {
        float mine = ts[tid];
        int r = 0;
        #pragma unroll
        for (int j = 0; j < K1; j++) {
            float tj = ts[j];
            r += (tj > mine) || (tj == mine && j < tid);
        }
        if (r < K2) nlist[r] = list[tid];
    }
    __syncthreads();
    if (tid < K2) list[tid] = nlist[tid];
    __syncthreads();

    // ============== pool + LayerNorm + classifier ==============
    if (tid < HC) {
        float acc = 0.f;
        #pragma unroll
        for (int i = 0; i < K2; i++) acc += tile[list[i] * HC + tid];
        sbuf[tid] = acc * gat[tid] * (1.0f / (float)K2);
    }
    __syncthreads();

    // LN partial sums over own 384 channels (warps 0-11)
    {
        float p1 = 0.f, p2 = 0.f;
        if (tid < HC) { float v = sbuf[tid]; p1 = v; p2 = v * v; }
        #pragma unroll
        for (int o = 16; o; o >>= 1) {
            p1 += __shfl_xor_sync(0xffffffffu, p1, o);
            p2 += __shfl_xor_sync(0xffffffffu, p2, o);
        }
        if (lane == 0) { red[warp] = p1; red[16 + warp] = p2; }
    }
    __syncthreads();
    if (tid == 0) {
        float s1 = 0.f, s2 = 0.f;
        #pragma unroll
        for (int w = 0; w < 12; w++) { s1 += red[w]; s2 += red[16 + w]; }
        xln[0] = s1; xln[1] = s2;
    }
    cluster_sync();                                   // #5
    if (tid == 0) {
        float s1 = xln[0] + peer_ldf(smem_u32(&xln[0]), peer);
        float s2 = xln[1] + peer_ldf(smem_u32(&xln[1]), peer);
        float m  = s1 * (1.0f / CH);
        float m2 = s2 * (1.0f / CH);
        red[30] = m;
        red[31] = rsqrtf(m2 - m * m + 1e-5f);
    }
    __syncthreads();
    if (tid < HC) {
        float mu = red[30], inv = red[31];
        gat[tid] = (sbuf[tid] - mu) * inv * ln_g[hb + tid] + ln_b[hb + tid];
    }
    __syncthreads();

    // classifier partials over own channels (warps 0-4)
    if (warp < 5) {
        const float* wr = g_clswt + warp * CH + hb;
        float acc = 0.f;
        #pragma unroll
        for (int k = 0; k < HC / 32; k++)
            acc += gat[lane + 32 * k] * wr[lane + 32 * k];
        #pragma unroll
        for (int o = 16; o; o >>= 1) acc += __shfl_xor_sync(0xffffffffu, acc, o);
        if (lane == 0) xcls[warp] = acc;
    }
    cluster_sync();                                   // #6
    if (rank == 0 && tid < 5)
        out[b * 5 + tid] = xcls[tid] + peer_ldf(smem_u32(&xcls[tid]), peer) + cls_b[tid];
    cluster_sync();                                   // #7 (peer smem stays alive)
}

extern "C" void kernel_launch(void* const* d_in, const int* in_sizes, int n_in,
                              void* d_out, int out_size) {
    const float* x    = (const float*)d_in[0];
    const float* w1a  = (const float*)d_in[1];
    const float* b1a  = (const float*)d_in[2];
    const float* w2a  = (const float*)d_in[3];
    const float* b2a  = (const float*)d_in[4];
    const float* w1b  = (const float*)d_in[5];
    const float* b1b  = (const float*)d_in[6];
    const float* w2b  = (const float*)d_in[7];
    const float* b2b  = (const float*)d_in[8];
    const float* lng  = (const float*)d_in[9];
    const float* lnb  = (const float*)d_in[10];
    const float* clsw = (const float*)d_in[11];
    const float* clsb = (const float*)d_in[12];
    float* out = (float*)d_out;

    static_assert(SM_BYTES < 113000, "need 2 CTAs per SM");
    cudaFuncSetAttribute(coatgft_kernel,
                         cudaFuncAttributeMaxDynamicSharedMemorySize, SM_BYTES);

    convert_weights_kernel<<<(MID * CH + 255) / 256, 256>>>(w1a, w2a, w1b, w2b, clsw);
    coatgft_kernel<<<2 * BATCH, THREADS, SM_BYTES>>>(x, b1a, b2a, b1b, b2b,
                                                     lng, lnb, clsb, out);
}